// round 2
// baseline (speedup 1.0000x reference)
#include <cuda_runtime.h>
#include <cstdint>

#define M_TOK 8192
#define K_DIM 4096
#define N_OUT 4096
#define NGRP  16
#define GSZ   256

#define BM 128
#define BN 64
#define BK 64
#define ASTRIDE 80   // padded smem row stride (bytes): conflict-free for frag LDS

// ---- scratch (device globals; no allocation allowed) ----
__device__ __align__(16) int8_t g_q[(size_t)M_TOK * K_DIM];     // quantized activations
__device__ float g_sx[M_TOK];                                    // per-token scale
__device__ float g_zp[M_TOK];                                    // per-token zero point
__device__ __align__(16) int8_t g_wz[(size_t)N_OUT * K_DIM];    // w - zeros (int8)
__device__ float g_wsum[N_OUT];                                  // sum_g s[o,g]*colsum_g

// ============================================================================
// Kernel 1: per-token asymmetric int8 quantization (matches torchao math)
// ============================================================================
__global__ __launch_bounds__(256) void quant_kernel(const float* __restrict__ x) {
    int row = blockIdx.x;
    int tid = threadIdx.x;
    const float4* xr4 = reinterpret_cast<const float4*>(x + (size_t)row * K_DIM) + tid * 4;

    float4 v[4];
#pragma unroll
    for (int i = 0; i < 4; i++) v[i] = xr4[i];

    float mn = 0.0f, mx = 0.0f;   // min(.,0) / max(.,0) folded into init
#pragma unroll
    for (int i = 0; i < 4; i++) {
        mn = fminf(mn, fminf(fminf(v[i].x, v[i].y), fminf(v[i].z, v[i].w)));
        mx = fmaxf(mx, fmaxf(fmaxf(v[i].x, v[i].y), fmaxf(v[i].z, v[i].w)));
    }
#pragma unroll
    for (int off = 16; off; off >>= 1) {
        mn = fminf(mn, __shfl_xor_sync(0xffffffffu, mn, off));
        mx = fmaxf(mx, __shfl_xor_sync(0xffffffffu, mx, off));
    }
    __shared__ float smn[8], smx[8];
    if ((tid & 31) == 0) { smn[tid >> 5] = mn; smx[tid >> 5] = mx; }
    __syncthreads();
    mn = smn[0]; mx = smx[0];
#pragma unroll
    for (int i = 1; i < 8; i++) { mn = fminf(mn, smn[i]); mx = fmaxf(mx, smx[i]); }

    float scale = fmaxf((mx - mn) / 255.0f, 1.1920928955078125e-07f);
    float a = mn / scale, b = mx / scale;
    float t = (-128.0f + a) + (127.0f + b);
    float zp0 = (t > 0.0f) ? (-128.0f - a) : (127.0f - b);
    float zpf = fminf(fmaxf(rintf(zp0), -128.0f), 127.0f);

    const float* pv = reinterpret_cast<const float*>(v);
    uint32_t packed[4];
#pragma unroll
    for (int w = 0; w < 4; w++) {
        uint32_t p = 0;
#pragma unroll
        for (int j = 0; j < 4; j++) {
            float qf = rintf(pv[w * 4 + j] / scale) + zpf;  // rintf = round-half-even (matches jnp.round)
            qf = fminf(fmaxf(qf, -128.0f), 127.0f);
            int qi = (int)qf;
            p |= (uint32_t)(uint8_t)(int8_t)qi << (8 * j);
        }
        packed[w] = p;
    }
    reinterpret_cast<uint4*>(g_q + (size_t)row * K_DIM)[tid] =
        make_uint4(packed[0], packed[1], packed[2], packed[3]);
    if (tid == 0) { g_sx[row] = scale; g_zp[row] = zpf; }
}

// ============================================================================
// Kernel 2: weight prep — weights arrive as INT32 (harness upcasts int8).
// wz = w - zeros (int8 scratch), Wsum[o] = sum_g s[o,g]*colsum_g(wz)
// ============================================================================
__global__ __launch_bounds__(256) void wprep_kernel(const int* __restrict__ W,
                                                    const float* __restrict__ scales,
                                                    const float* __restrict__ zeros) {
    int o = blockIdx.x;
    int tid = threadIdx.x;
    int g = tid >> 4;                               // 16 elements/thread => one group per 16 threads
    int zi = __float2int_rn(zeros[o * NGRP + g]);

    const int4* Wrow = reinterpret_cast<const int4*>(W + (size_t)o * K_DIM) + tid * 4;
    uint32_t ow[4];
    int s = 0;
#pragma unroll
    for (int c = 0; c < 4; c++) {
        int4 w4 = Wrow[c];                           // 4 int32 weights
        int v0 = w4.x - zi, v1 = w4.y - zi, v2 = w4.z - zi, v3 = w4.w - zi;  // in [-15,15]
        s += v0 + v1 + v2 + v3;
        ow[c] = ((uint32_t)(uint8_t)(int8_t)v0)
              | ((uint32_t)(uint8_t)(int8_t)v1 << 8)
              | ((uint32_t)(uint8_t)(int8_t)v2 << 16)
              | ((uint32_t)(uint8_t)(int8_t)v3 << 24);
    }
    reinterpret_cast<uint4*>(g_wz + (size_t)o * K_DIM)[tid] =
        make_uint4(ow[0], ow[1], ow[2], ow[3]);

    __shared__ int ssum[256];
    __shared__ float gs[NGRP];
    ssum[tid] = s;
    __syncthreads();
    if (tid < NGRP) {
        int cs = 0;
#pragma unroll
        for (int j = 0; j < 16; j++) cs += ssum[tid * 16 + j];
        gs[tid] = scales[o * NGRP + tid] * (float)cs;
    }
    __syncthreads();
    if (tid == 0) {
        float acc = 0.0f;
#pragma unroll
        for (int j = 0; j < NGRP; j++) acc += gs[j];
        g_wsum[o] = acc;
    }
}

// ============================================================================
// Kernel 3: group-scaled int8 GEMM (m16n8k32 s8 IMMA) + fused epilogue
// ============================================================================
__device__ __forceinline__ void mma_s8(int& c0, int& c1, int& c2, int& c3,
                                       uint32_t a0, uint32_t a1, uint32_t a2, uint32_t a3,
                                       uint32_t b0, uint32_t b1) {
    asm volatile(
        "mma.sync.aligned.m16n8k32.row.col.s32.s8.s8.s32 "
        "{%0,%1,%2,%3}, {%4,%5,%6,%7}, {%8,%9}, {%0,%1,%2,%3};\n"
        : "+r"(c0), "+r"(c1), "+r"(c2), "+r"(c3)
        : "r"(a0), "r"(a1), "r"(a2), "r"(a3), "r"(b0), "r"(b1));
}

__global__ __launch_bounds__(256, 2) void gemm_kernel(const float* __restrict__ scales,
                                                      float* __restrict__ out) {
    __shared__ __align__(16) int8_t As[BM * ASTRIDE];
    __shared__ __align__(16) int8_t Bs[BN * ASTRIDE];
    __shared__ float Ss[NGRP * BN];   // [g][col] transposed for conflict-free fold reads

    int tid = threadIdx.x;
    int lane = tid & 31, wid = tid >> 5;
    int warpm = wid & 3, warpn = wid >> 2;        // 4 x 2 warp grid, warp tile 32x32
    int gid = lane >> 2, tig = lane & 3;
    int bm = blockIdx.y, bn = blockIdx.x;

    for (int i = tid; i < NGRP * BN; i += 256) {
        int g = i >> 6, col = i & 63;
        Ss[i] = scales[(size_t)(bn * BN + col) * NGRP + g];
    }

    int c[2][4][4];
    float f[2][4][4];
#pragma unroll
    for (int mt = 0; mt < 2; mt++)
#pragma unroll
        for (int nt = 0; nt < 4; nt++)
#pragma unroll
            for (int r = 0; r < 4; r++) { c[mt][nt][r] = 0; f[mt][nt][r] = 0.0f; }

    const int8_t* Ag = g_q + (size_t)bm * BM * K_DIM;
    const int8_t* Bg = g_wz + (size_t)bn * BN * K_DIM;

    for (int kc = 0; kc < K_DIM / BK; ++kc) {
        // stage A tile: 128 x 64 bytes
#pragma unroll
        for (int it = 0; it < 2; ++it) {
            int idx = tid + it * 256;
            int r = idx >> 2, cq = idx & 3;
            uint4 v = *reinterpret_cast<const uint4*>(Ag + (size_t)r * K_DIM + kc * BK + cq * 16);
            *reinterpret_cast<uint4*>(As + r * ASTRIDE + cq * 16) = v;
        }
        // stage B tile: 64 x 64 bytes
        {
            int r = tid >> 2, cq = tid & 3;
            uint4 v = *reinterpret_cast<const uint4*>(Bg + (size_t)r * K_DIM + kc * BK + cq * 16);
            *reinterpret_cast<uint4*>(Bs + r * ASTRIDE + cq * 16) = v;
        }
        __syncthreads();

#pragma unroll
        for (int ks = 0; ks < 2; ++ks) {
            uint32_t a[2][4], b[4][2];
#pragma unroll
            for (int mt = 0; mt < 2; ++mt) {
                int r0 = warpm * 32 + mt * 16 + gid;
                const int8_t* base = As + ks * 32 + tig * 4;
                a[mt][0] = *reinterpret_cast<const uint32_t*>(base + r0 * ASTRIDE);
                a[mt][1] = *reinterpret_cast<const uint32_t*>(base + (r0 + 8) * ASTRIDE);
                a[mt][2] = *reinterpret_cast<const uint32_t*>(base + r0 * ASTRIDE + 16);
                a[mt][3] = *reinterpret_cast<const uint32_t*>(base + (r0 + 8) * ASTRIDE + 16);
            }
#pragma unroll
            for (int nt = 0; nt < 4; ++nt) {
                int cb = warpn * 32 + nt * 8 + gid;
                const int8_t* base = Bs + cb * ASTRIDE + ks * 32 + tig * 4;
                b[nt][0] = *reinterpret_cast<const uint32_t*>(base);
                b[nt][1] = *reinterpret_cast<const uint32_t*>(base + 16);
            }
#pragma unroll
            for (int mt = 0; mt < 2; ++mt)
#pragma unroll
                for (int nt = 0; nt < 4; ++nt)
                    mma_s8(c[mt][nt][0], c[mt][nt][1], c[mt][nt][2], c[mt][nt][3],
                           a[mt][0], a[mt][1], a[mt][2], a[mt][3],
                           b[nt][0], b[nt][1]);
        }
        __syncthreads();

        // group boundary every 4 k-chunks (256 K): fold exact int acc into fp32
        if ((kc & 3) == 3) {
            int g = kc >> 2;
#pragma unroll
            for (int nt = 0; nt < 4; ++nt) {
                int col = warpn * 32 + nt * 8 + tig * 2;
                float s0 = Ss[g * BN + col];
                float s1 = Ss[g * BN + col + 1];
#pragma unroll
                for (int mt = 0; mt < 2; ++mt) {
                    f[mt][nt][0] = fmaf((float)c[mt][nt][0], s0, f[mt][nt][0]);
                    f[mt][nt][1] = fmaf((float)c[mt][nt][1], s1, f[mt][nt][1]);
                    f[mt][nt][2] = fmaf((float)c[mt][nt][2], s0, f[mt][nt][2]);
                    f[mt][nt][3] = fmaf((float)c[mt][nt][3], s1, f[mt][nt][3]);
                    c[mt][nt][0] = c[mt][nt][1] = c[mt][nt][2] = c[mt][nt][3] = 0;
                }
            }
        }
    }

    // epilogue: out[m,o] = sx[m]*(facc - zp[m]*Wsum[o])
#pragma unroll
    for (int mt = 0; mt < 2; ++mt) {
        int rlo = bm * BM + warpm * 32 + mt * 16 + gid;
        int rhi = rlo + 8;
        float sxl = g_sx[rlo], zl = g_zp[rlo];
        float sxh = g_sx[rhi], zh = g_zp[rhi];
#pragma unroll
        for (int nt = 0; nt < 4; ++nt) {
            int o0 = bn * BN + warpn * 32 + nt * 8 + tig * 2;
            float w0 = g_wsum[o0], w1 = g_wsum[o0 + 1];
            float2 vlo = make_float2(sxl * (f[mt][nt][0] - zl * w0),
                                     sxl * (f[mt][nt][1] - zl * w1));
            float2 vhi = make_float2(sxh * (f[mt][nt][2] - zh * w0),
                                     sxh * (f[mt][nt][3] - zh * w1));
            *reinterpret_cast<float2*>(out + (size_t)rlo * N_OUT + o0) = vlo;
            *reinterpret_cast<float2*>(out + (size_t)rhi * N_OUT + o0) = vhi;
        }
    }
}

// ============================================================================
// launch
// ============================================================================
extern "C" void kernel_launch(void* const* d_in, const int* in_sizes, int n_in,
                              void* d_out, int out_size) {
    const float* x      = (const float*)d_in[0];
    const int*   w      = (const int*)d_in[1];     // int8 upcast to int32 by harness
    const float* scales = (const float*)d_in[2];
    const float* zeros  = (const float*)d_in[3];
    float* out = (float*)d_out;

    quant_kernel<<<M_TOK, 256>>>(x);
    wprep_kernel<<<N_OUT, 256>>>(w, scales, zeros);
    gemm_kernel<<<dim3(N_OUT / BN, M_TOK / BM), 256>>>(scales, out);
}